// round 3
// baseline (speedup 1.0000x reference)
#include <cuda_runtime.h>

// Problem constants
#define N_ROWS 131072   // B*T = 64*2048
#define DIM    64
#define KST    4
#define CCNT   1024
#define CHUNK  128      // centroids staged in smem per iteration
#define TPB    256

__device__ float  g_cbnorm[KST * CCNT];
__device__ double g_loss_acc;

// Zero count region + loss accumulator (must run every call: graph replays).
__global__ void rq_zero(float* counts, int n) {
    int i = blockIdx.x * blockDim.x + threadIdx.x;
    if (i < n) counts[i] = 0.0f;
    if (i == 0) g_loss_acc = 0.0;
}

// Precompute ||c||^2 per centroid.
__global__ void rq_cbnorm(const float* __restrict__ cb) {
    int c = blockIdx.x * blockDim.x + threadIdx.x;   // 0..4095
    const float4* p = (const float4*)(cb + (size_t)c * DIM);
    float s = 0.0f;
#pragma unroll
    for (int i = 0; i < 16; i++) {
        float4 v = p[i];
        s = fmaf(v.x, v.x, s); s = fmaf(v.y, v.y, s);
        s = fmaf(v.z, v.z, s); s = fmaf(v.w, v.w, s);
    }
    g_cbnorm[c] = s;
}

__global__ void __launch_bounds__(TPB)
rq_main(const float* __restrict__ inputs,
        const float* __restrict__ codebooks,
        float* __restrict__ out_quant,
        float* __restrict__ out_idx,
        float* __restrict__ out_counts) {
    __shared__ float4 scb[CHUNK * 16];   // 32 KB: 128 centroids x 64 floats
    __shared__ float  scbn[CHUNK];
    __shared__ float  sred[TPB];

    const int tid = threadIdx.x;
    const int row = blockIdx.x * TPB + tid;   // grid is exactly N_ROWS/TPB

    const float4* inp = (const float4*)(inputs + (size_t)row * DIM);
    float res[DIM];   // residual in registers (plain scalar)
#pragma unroll
    for (int i = 0; i < 16; i++) {
        float4 v = inp[i];
        res[4*i]   = v.x;
        res[4*i+1] = v.y;
        res[4*i+2] = v.z;
        res[4*i+3] = v.w;
    }

    float loss_t = 0.0f;

    for (int k = 0; k < KST; k++) {
        const float* cbk = codebooks + (size_t)k * CCNT * DIM;
        float best = 3.4e38f;
        int   bi   = 0;

        for (int ch = 0; ch < CCNT / CHUNK; ch++) {
            __syncthreads();
            const float4* src = (const float4*)(cbk + (size_t)ch * CHUNK * DIM);
#pragma unroll
            for (int j = 0; j < (CHUNK * 16) / TPB; j++)
                scb[tid + j * TPB] = src[tid + j * TPB];
            if (tid < CHUNK)
                scbn[tid] = g_cbnorm[k * CCNT + ch * CHUNK + tid];
            __syncthreads();

#pragma unroll 1
            for (int cc = 0; cc < CHUNK; cc++) {
                const float4* cp = scb + cc * 16;
                float a0 = 0.f, a1 = 0.f, a2 = 0.f, a3 = 0.f;
#pragma unroll
                for (int i = 0; i < 16; i++) {
                    float4 c = cp[i];
                    a0 = fmaf(c.x, res[4*i],   a0);
                    a1 = fmaf(c.y, res[4*i+1], a1);
                    a2 = fmaf(c.z, res[4*i+2], a2);
                    a3 = fmaf(c.w, res[4*i+3], a3);
                }
                float score = fmaf(-2.0f, (a0 + a1) + (a2 + a3), scbn[cc]);
                if (score < best) { best = score; bi = ch * CHUNK + cc; }
            }
        }

        // Fetch chosen centroid (L2-resident), update residual, accumulate loss.
        const float4* cb = (const float4*)(cbk + (size_t)bi * DIM);
        float l = 0.0f;
#pragma unroll
        for (int i = 0; i < 16; i++) {
            float4 c = cb[i];
            float d0 = c.x - res[4*i];
            float d1 = c.y - res[4*i+1];
            float d2 = c.z - res[4*i+2];
            float d3 = c.w - res[4*i+3];
            l = fmaf(d0, d0, l); l = fmaf(d1, d1, l);
            l = fmaf(d2, d2, l); l = fmaf(d3, d3, l);
            res[4*i]   = -d0;
            res[4*i+1] = -d1;
            res[4*i+2] = -d2;
            res[4*i+3] = -d3;
        }
        loss_t += l;
        out_idx[k * N_ROWS + row] = (float)bi;
        atomicAdd(&out_counts[k * CCNT + bi], 1.0f);
    }

    // quantized = input - final residual (telescoped sum of stage quants)
    float4* oq = (float4*)(out_quant + (size_t)row * DIM);
#pragma unroll
    for (int i = 0; i < 16; i++) {
        float4 v = inp[i];
        float4 q;
        q.x = v.x - res[4*i];
        q.y = v.y - res[4*i+1];
        q.z = v.z - res[4*i+2];
        q.w = v.w - res[4*i+3];
        oq[i] = q;
    }

    // Block-reduce loss, one double atomic per block (order-insensitive to fp32 noise).
    sred[tid] = loss_t;
    __syncthreads();
    for (int s = TPB / 2; s > 0; s >>= 1) {
        if (tid < s) sred[tid] += sred[tid + s];
        __syncthreads();
    }
    if (tid == 0) atomicAdd(&g_loss_acc, (double)sred[0]);
}

__global__ void rq_loss_bcast(float* __restrict__ out_loss) {
    int i = blockIdx.x * blockDim.x + threadIdx.x;
    out_loss[i] = (float)(g_loss_acc / ((double)N_ROWS * (double)DIM));
}

extern "C" void kernel_launch(void* const* d_in, const int* in_sizes, int n_in,
                              void* d_out, int out_size) {
    // Bind inputs by SIZE (robust to ordering): inputs = 8388608 f32,
    // codebooks = 262144 f32.
    const float* inputs;
    const float* codebooks;
    if (in_sizes[0] == N_ROWS * DIM) {
        inputs    = (const float*)d_in[0];
        codebooks = (const float*)d_in[1];
    } else {
        codebooks = (const float*)d_in[0];
        inputs    = (const float*)d_in[1];
    }
    float* out = (float*)d_out;

    // Output layout (concatenated, reference return order, all float32):
    // quantized [B,T,D] | quantization_loss [B,T,1] | nn_idx [K,B,T] |
    // codebooks_out [K*C,D] | counts [K,C]
    float* out_quant  = out;                            // 8388608
    float* out_loss   = out + 8388608;                  // 131072
    float* out_idx    = out + 8388608 + 131072;         // 524288
    float* out_cb     = out + 8388608 + 131072 + 524288;          // 262144
    float* out_counts = out + 8388608 + 131072 + 524288 + 262144; // 4096

    rq_zero<<<(KST * CCNT + 255) / 256, 256>>>(out_counts, KST * CCNT);
    rq_cbnorm<<<(KST * CCNT) / 256, 256>>>(codebooks);
    rq_main<<<N_ROWS / TPB, TPB>>>(inputs, codebooks, out_quant, out_idx, out_counts);
    rq_loss_bcast<<<N_ROWS / 256, 256>>>(out_loss);
    cudaMemcpyAsync(out_cb, codebooks, (size_t)KST * CCNT * DIM * sizeof(float),
                    cudaMemcpyDeviceToDevice);
}

// round 4
// speedup vs baseline: 1.1958x; 1.1958x over previous
#include <cuda_runtime.h>

// Problem constants
#define N_ROWS 131072   // B*T = 64*2048
#define DIM    64
#define KST    4
#define CCNT   1024
#define CHUNK  128      // centroids staged in smem per iteration
#define TPB    256

typedef unsigned long long ull;

__device__ float  g_cbnorm[KST * CCNT];
__device__ double g_loss_acc;

__device__ __forceinline__ ull pk2(float x, float y) {
    ull r; asm("mov.b64 %0, {%1, %2};" : "=l"(r) : "f"(x), "f"(y)); return r;
}
__device__ __forceinline__ float2 upk2(ull v) {
    float2 r; asm("mov.b64 {%0, %1}, %2;" : "=f"(r.x), "=f"(r.y) : "l"(v)); return r;
}
// Functional packed FMA: acc = c*r + acc (elementwise on packed f32 pairs).
__device__ __forceinline__ ull fma2(ull c, ull r, ull acc) {
    ull d;
    asm("fma.rn.f32x2 %0, %1, %2, %3;" : "=l"(d) : "l"(c), "l"(r), "l"(acc));
    return d;
}
__device__ __forceinline__ ull add2(ull a, ull b) {
    ull d;
    asm("add.rn.f32x2 %0, %1, %2;" : "=l"(d) : "l"(a), "l"(b));
    return d;
}

// Prep: zero counts + loss accumulator, compute ||c||^2 per centroid.
// Must run every call (graph replays). 4096 threads.
__global__ void rq_prep(const float* __restrict__ cb, float* counts) {
    int c = blockIdx.x * blockDim.x + threadIdx.x;   // 0..4095
    counts[c] = 0.0f;
    if (c == 0) g_loss_acc = 0.0;
    const float4* p = (const float4*)(cb + (size_t)c * DIM);
    float s = 0.0f;
#pragma unroll
    for (int i = 0; i < 16; i++) {
        float4 v = p[i];
        s = fmaf(v.x, v.x, s); s = fmaf(v.y, v.y, s);
        s = fmaf(v.z, v.z, s); s = fmaf(v.w, v.w, s);
    }
    g_cbnorm[c] = s;
}

__global__ void __launch_bounds__(TPB, 2)
rq_main(const float* __restrict__ inputs,
        const float* __restrict__ codebooks,
        float* __restrict__ out_quant,
        float* __restrict__ out_idx,
        float* __restrict__ out_counts) {
    // Shared codebook chunk, declared AND accessed as ulonglong2 (f32 pairs).
    __shared__ ulonglong2 scb[CHUNK * 16];   // 32 KB: 128 centroids x 64 floats
    __shared__ float      scbn[CHUNK];
    __shared__ float      sred[TPB];

    const int tid = threadIdx.x;
    const int row = blockIdx.x * TPB + tid;   // grid is exactly N_ROWS/TPB

    const float4* inp = (const float4*)(inputs + (size_t)row * DIM);
    float res[DIM];   // scalar residual (authoritative, same as passing R3)
#pragma unroll
    for (int i = 0; i < 16; i++) {
        float4 v = inp[i];
        res[4*i]   = v.x;
        res[4*i+1] = v.y;
        res[4*i+2] = v.z;
        res[4*i+3] = v.w;
    }

    float loss_t = 0.0f;

    for (int k = 0; k < KST; k++) {
        const float* cbk = codebooks + (size_t)k * CCNT * DIM;
        float best = 3.4e38f;
        int   bi   = 0;

        // Packed copy of the residual for this stage (32 f32x2 pairs).
        ull r2[32];
#pragma unroll
        for (int i = 0; i < 32; i++)
            r2[i] = pk2(res[2*i], res[2*i+1]);

        for (int ch = 0; ch < CCNT / CHUNK; ch++) {
            __syncthreads();
            const ulonglong2* src =
                (const ulonglong2*)(cbk + (size_t)ch * CHUNK * DIM);
#pragma unroll
            for (int j = 0; j < (CHUNK * 16) / TPB; j++)
                scb[tid + j * TPB] = src[tid + j * TPB];
            if (tid < CHUNK)
                scbn[tid] = g_cbnorm[k * CCNT + ch * CHUNK + tid];
            __syncthreads();

#pragma unroll 1
            for (int cc = 0; cc < CHUNK; cc++) {
                const ulonglong2* cp = scb + cc * 16;
                ull a0 = 0, a1 = 0, a2 = 0, a3 = 0;
#pragma unroll
                for (int i = 0; i < 8; i++) {
                    ulonglong2 c0 = cp[2*i];
                    ulonglong2 c1 = cp[2*i + 1];
                    a0 = fma2(c0.x, r2[4*i],   a0);
                    a1 = fma2(c0.y, r2[4*i+1], a1);
                    a2 = fma2(c1.x, r2[4*i+2], a2);
                    a3 = fma2(c1.y, r2[4*i+3], a3);
                }
                ull s01 = add2(a0, a1);
                ull s23 = add2(a2, a3);
                ull st  = add2(s01, s23);
                float2 s = upk2(st);
                float score = fmaf(-2.0f, s.x + s.y, scbn[cc]);
                if (score < best) { best = score; bi = ch * CHUNK + cc; }
            }
        }

        // Fetch chosen centroid (L2-resident), update residual, accumulate loss.
        const float4* cb = (const float4*)(cbk + (size_t)bi * DIM);
        float l = 0.0f;
#pragma unroll
        for (int i = 0; i < 16; i++) {
            float4 c = cb[i];
            float d0 = c.x - res[4*i];
            float d1 = c.y - res[4*i+1];
            float d2 = c.z - res[4*i+2];
            float d3 = c.w - res[4*i+3];
            l = fmaf(d0, d0, l); l = fmaf(d1, d1, l);
            l = fmaf(d2, d2, l); l = fmaf(d3, d3, l);
            res[4*i]   = -d0;
            res[4*i+1] = -d1;
            res[4*i+2] = -d2;
            res[4*i+3] = -d3;
        }
        loss_t += l;
        out_idx[k * N_ROWS + row] = (float)bi;
        atomicAdd(&out_counts[k * CCNT + bi], 1.0f);
    }

    // quantized = input - final residual (telescoped sum of stage quants)
    float4* oq = (float4*)(out_quant + (size_t)row * DIM);
#pragma unroll
    for (int i = 0; i < 16; i++) {
        float4 v = inp[i];
        float4 q;
        q.x = v.x - res[4*i];
        q.y = v.y - res[4*i+1];
        q.z = v.z - res[4*i+2];
        q.w = v.w - res[4*i+3];
        oq[i] = q;
    }

    // Block-reduce loss, one double atomic per block.
    sred[tid] = loss_t;
    __syncthreads();
    for (int s = TPB / 2; s > 0; s >>= 1) {
        if (tid < s) sred[tid] += sred[tid + s];
        __syncthreads();
    }
    if (tid == 0) atomicAdd(&g_loss_acc, (double)sred[0]);
}

__global__ void rq_loss_bcast(float* __restrict__ out_loss) {
    int i = blockIdx.x * blockDim.x + threadIdx.x;
    out_loss[i] = (float)(g_loss_acc / ((double)N_ROWS * (double)DIM));
}

__global__ void rq_cbcopy(const float4* __restrict__ src, float4* __restrict__ dst) {
    int i = blockIdx.x * blockDim.x + threadIdx.x;   // 65536 float4s
    dst[i] = src[i];
}

extern "C" void kernel_launch(void* const* d_in, const int* in_sizes, int n_in,
                              void* d_out, int out_size) {
    // Bind inputs by SIZE: inputs = 8388608 f32, codebooks = 262144 f32.
    const float* inputs;
    const float* codebooks;
    if (in_sizes[0] == N_ROWS * DIM) {
        inputs    = (const float*)d_in[0];
        codebooks = (const float*)d_in[1];
    } else {
        codebooks = (const float*)d_in[0];
        inputs    = (const float*)d_in[1];
    }
    float* out = (float*)d_out;

    // Output layout (reference return order, all float32):
    // quantized [B,T,D] | quantization_loss [B,T,1] | nn_idx [K,B,T] |
    // codebooks_out [K*C,D] | counts [K,C]
    float* out_quant  = out;                            // 8388608
    float* out_loss   = out + 8388608;                  // 131072
    float* out_idx    = out + 8388608 + 131072;         // 524288
    float* out_cb     = out + 8388608 + 131072 + 524288;          // 262144
    float* out_counts = out + 8388608 + 131072 + 524288 + 262144; // 4096

    // 4 kernels per call, rq_main second => ncu (-s 5 -c 1) captures rq_main.
    rq_prep<<<(KST * CCNT) / 256, 256>>>(codebooks, out_counts);
    rq_main<<<N_ROWS / TPB, TPB>>>(inputs, codebooks, out_quant, out_idx, out_counts);
    rq_loss_bcast<<<N_ROWS / 256, 256>>>(out_loss);
    rq_cbcopy<<<(KST * CCNT * DIM / 4) / 256, 256>>>((const float4*)codebooks,
                                                     (float4*)out_cb);
}

// round 5
// speedup vs baseline: 1.2258x; 1.0251x over previous
#include <cuda_runtime.h>

// Problem constants
#define N_ROWS 131072   // B*T = 64*2048
#define DIM    64
#define KST    4
#define CCNT   1024
#define CHUNK  128      // centroids staged in smem per iteration
#define TPB    256
#define NBLK   (N_ROWS / TPB)   // 512

typedef unsigned long long ull;

__device__ float        g_cbnorm[KST * CCNT];
__device__ double       g_loss_acc;
__device__ unsigned int g_ticket;

__device__ __forceinline__ ull pk2(float x, float y) {
    ull r; asm("mov.b64 %0, {%1, %2};" : "=l"(r) : "f"(x), "f"(y)); return r;
}
__device__ __forceinline__ float2 upk2(ull v) {
    float2 r; asm("mov.b64 {%0, %1}, %2;" : "=f"(r.x), "=f"(r.y) : "l"(v)); return r;
}
// Functional packed FMA: d = c*r + acc (elementwise on packed f32 pairs).
__device__ __forceinline__ ull fma2(ull c, ull r, ull acc) {
    ull d;
    asm("fma.rn.f32x2 %0, %1, %2, %3;" : "=l"(d) : "l"(c), "l"(r), "l"(acc));
    return d;
}
__device__ __forceinline__ ull add2(ull a, ull b) {
    ull d;
    asm("add.rn.f32x2 %0, %1, %2;" : "=l"(d) : "l"(a), "l"(b));
    return d;
}

// Prep: zero counts/ticket/loss, compute ||c||^2 per centroid. Runs every call.
__global__ void rq_prep(const float* __restrict__ cb, float* counts) {
    int c = blockIdx.x * blockDim.x + threadIdx.x;   // 0..4095
    counts[c] = 0.0f;
    if (c == 0) { g_loss_acc = 0.0; g_ticket = 0u; }
    const float4* p = (const float4*)(cb + (size_t)c * DIM);
    float s = 0.0f;
#pragma unroll
    for (int i = 0; i < 16; i++) {
        float4 v = p[i];
        s = fmaf(v.x, v.x, s); s = fmaf(v.y, v.y, s);
        s = fmaf(v.z, v.z, s); s = fmaf(v.w, v.w, s);
    }
    g_cbnorm[c] = s;
}

__global__ void rq_cbcopy(const float4* __restrict__ src, float4* __restrict__ dst) {
    int i = blockIdx.x * blockDim.x + threadIdx.x;   // 65536 float4s
    dst[i] = src[i];
}

__global__ void __launch_bounds__(TPB, 2)
rq_main(const float* __restrict__ inputs,
        const float* __restrict__ codebooks,
        float* __restrict__ out_quant,
        float* __restrict__ out_idx,
        float* __restrict__ out_counts,
        float* __restrict__ out_loss) {
    // Shared codebook chunk, declared AND accessed as ulonglong2 (f32 pairs).
    __shared__ ulonglong2 scb[CHUNK * 16];   // 32 KB: 128 centroids x 64 floats
    __shared__ float      scbn[CHUNK];
    __shared__ float      sred[TPB];
    __shared__ float      s_lossval;

    const int tid = threadIdx.x;
    const int row = blockIdx.x * TPB + tid;

    // Residual: ONLY packed representation (32 f32x2 pairs = 64 regs).
    ull r2[32];
    {
        const float4* inp = (const float4*)(inputs + (size_t)row * DIM);
#pragma unroll
        for (int i = 0; i < 16; i++) {
            float4 v = inp[i];
            r2[2*i]   = pk2(v.x, v.y);
            r2[2*i+1] = pk2(v.z, v.w);
        }
    }

    float loss_t = 0.0f;

    for (int k = 0; k < KST; k++) {
        const float* cbk = codebooks + (size_t)k * CCNT * DIM;
        float best = 3.4e38f;
        int   bi   = 0;

        for (int ch = 0; ch < CCNT / CHUNK; ch++) {
            __syncthreads();
            const ulonglong2* src =
                (const ulonglong2*)(cbk + (size_t)ch * CHUNK * DIM);
#pragma unroll
            for (int j = 0; j < (CHUNK * 16) / TPB; j++)
                scb[tid + j * TPB] = src[tid + j * TPB];
            if (tid < CHUNK)
                scbn[tid] = g_cbnorm[k * CCNT + ch * CHUNK + tid];
            __syncthreads();

#pragma unroll 2
            for (int cc = 0; cc < CHUNK; cc++) {
                const ulonglong2* cp = scb + cc * 16;
                ull a0 = 0, a1 = 0, a2 = 0, a3 = 0;
#pragma unroll
                for (int i = 0; i < 8; i++) {
                    ulonglong2 c0 = cp[2*i];
                    ulonglong2 c1 = cp[2*i + 1];
                    a0 = fma2(c0.x, r2[4*i],   a0);
                    a1 = fma2(c0.y, r2[4*i+1], a1);
                    a2 = fma2(c1.x, r2[4*i+2], a2);
                    a3 = fma2(c1.y, r2[4*i+3], a3);
                }
                ull st = add2(add2(a0, a1), add2(a2, a3));
                float2 s = upk2(st);
                float score = fmaf(-2.0f, s.x + s.y, scbn[cc]);
                if (score < best) { best = score; bi = ch * CHUNK + cc; }
            }
        }

        // Chosen centroid (L2-resident): update packed residual + loss.
        const float4* cb = (const float4*)(cbk + (size_t)bi * DIM);
        float l = 0.0f;
#pragma unroll
        for (int i = 0; i < 16; i++) {
            float4 c  = cb[i];
            float2 p0 = upk2(r2[2*i]);
            float2 p1 = upk2(r2[2*i+1]);
            float d0 = p0.x - c.x, d1 = p0.y - c.y;
            float d2 = p1.x - c.z, d3 = p1.y - c.w;
            l = fmaf(d0, d0, l); l = fmaf(d1, d1, l);
            l = fmaf(d2, d2, l); l = fmaf(d3, d3, l);
            r2[2*i]   = pk2(d0, d1);
            r2[2*i+1] = pk2(d2, d3);
        }
        loss_t += l;
        out_idx[k * N_ROWS + row] = (float)bi;
        atomicAdd(&out_counts[k * CCNT + bi], 1.0f);
    }

    // quantized = input - final residual (reload input; one streaming pass).
    {
        const float4* inp = (const float4*)(inputs + (size_t)row * DIM);
        float4* oq = (float4*)(out_quant + (size_t)row * DIM);
#pragma unroll
        for (int i = 0; i < 16; i++) {
            float4 v  = inp[i];
            float2 p0 = upk2(r2[2*i]);
            float2 p1 = upk2(r2[2*i+1]);
            float4 q;
            q.x = v.x - p0.x; q.y = v.y - p0.y;
            q.z = v.z - p1.x; q.w = v.w - p1.y;
            oq[i] = q;
        }
    }

    // Block-reduce loss, one double atomic per block.
    sred[tid] = loss_t;
    __syncthreads();
    for (int s = TPB / 2; s > 0; s >>= 1) {
        if (tid < s) sred[tid] += sred[tid + s];
        __syncthreads();
    }
    if (tid == 0) {
        atomicAdd(&g_loss_acc, (double)sred[0]);
        __threadfence();
        unsigned t = atomicAdd(&g_ticket, 1u);
        sred[0] = (t == (unsigned)(gridDim.x - 1)) ? 1.0f : 0.0f;
    }
    __syncthreads();

    // Last block to finish broadcasts the mean loss to all 131072 slots.
    if (sred[0] != 0.0f) {
        if (tid == 0) {
            double total = atomicAdd(&g_loss_acc, 0.0);   // all contributions visible
            s_lossval = (float)(total / ((double)N_ROWS * (double)DIM));
        }
        __syncthreads();
        float lv = s_lossval;
        float4 lv4 = make_float4(lv, lv, lv, lv);
        float4* ol = (float4*)out_loss;
        for (int i = tid; i < N_ROWS / 4; i += TPB)
            ol[i] = lv4;
    }
}

extern "C" void kernel_launch(void* const* d_in, const int* in_sizes, int n_in,
                              void* d_out, int out_size) {
    // Bind inputs by SIZE: inputs = 8388608 f32, codebooks = 262144 f32.
    const float* inputs;
    const float* codebooks;
    if (in_sizes[0] == N_ROWS * DIM) {
        inputs    = (const float*)d_in[0];
        codebooks = (const float*)d_in[1];
    } else {
        codebooks = (const float*)d_in[0];
        inputs    = (const float*)d_in[1];
    }
    float* out = (float*)d_out;

    // Output layout (reference return order, all float32):
    // quantized [B,T,D] | quantization_loss [B,T,1] | nn_idx [K,B,T] |
    // codebooks_out [K*C,D] | counts [K,C]
    float* out_quant  = out;                            // 8388608
    float* out_loss   = out + 8388608;                  // 131072
    float* out_idx    = out + 8388608 + 131072;         // 524288
    float* out_cb     = out + 8388608 + 131072 + 524288;          // 262144
    float* out_counts = out + 8388608 + 131072 + 524288 + 262144; // 4096

    // 3 launches per call, rq_main LAST (ncu -s 5 -c 1 lands on it).
    rq_prep<<<(KST * CCNT) / 256, 256>>>(codebooks, out_counts);
    rq_cbcopy<<<(KST * CCNT * DIM / 4) / 256, 256>>>((const float4*)codebooks,
                                                     (float4*)out_cb);
    rq_main<<<NBLK, TPB>>>(inputs, codebooks, out_quant, out_idx,
                           out_counts, out_loss);
}

// round 6
// speedup vs baseline: 1.4005x; 1.1425x over previous
#include <cuda_runtime.h>

// Problem constants
#define N_ROWS 131072   // B*T = 64*2048
#define DIM    64
#define KST    4
#define CCNT   1024
#define CHUNK  128      // centroids staged in smem per iteration
#define TPB    128
#define NBLK   (N_ROWS / TPB)   // 1024

typedef unsigned long long ull;

__device__ float        g_cbnorm[KST * CCNT];
__device__ double       g_loss_acc;
__device__ unsigned int g_ticket;

__device__ __forceinline__ ull pk2(float x, float y) {
    ull r; asm("mov.b64 %0, {%1, %2};" : "=l"(r) : "f"(x), "f"(y)); return r;
}
__device__ __forceinline__ float2 upk2(ull v) {
    float2 r; asm("mov.b64 {%0, %1}, %2;" : "=f"(r.x), "=f"(r.y) : "l"(v)); return r;
}
__device__ __forceinline__ ull fma2(ull c, ull r, ull acc) {
    ull d;
    asm("fma.rn.f32x2 %0, %1, %2, %3;" : "=l"(d) : "l"(c), "l"(r), "l"(acc));
    return d;
}
__device__ __forceinline__ ull add2(ull a, ull b) {
    ull d;
    asm("add.rn.f32x2 %0, %1, %2;" : "=l"(d) : "l"(a), "l"(b));
    return d;
}

// Prep: zero counts/ticket/loss, compute ||c||^2 per centroid. Runs every call.
__global__ void rq_prep(const float* __restrict__ cb, float* counts) {
    int c = blockIdx.x * blockDim.x + threadIdx.x;   // 0..4095
    counts[c] = 0.0f;
    if (c == 0) { g_loss_acc = 0.0; g_ticket = 0u; }
    const float4* p = (const float4*)(cb + (size_t)c * DIM);
    float s = 0.0f;
#pragma unroll
    for (int i = 0; i < 16; i++) {
        float4 v = p[i];
        s = fmaf(v.x, v.x, s); s = fmaf(v.y, v.y, s);
        s = fmaf(v.z, v.z, s); s = fmaf(v.w, v.w, s);
    }
    g_cbnorm[c] = s;
}

__global__ void rq_cbcopy(const float4* __restrict__ src, float4* __restrict__ dst) {
    int i = blockIdx.x * blockDim.x + threadIdx.x;   // 65536 float4s
    dst[i] = src[i];
}

// Filler (3rd launch so rq_main is #4 for ncu): pre-zero loss slots (benign,
// overwritten by rq_main's final block).
__global__ void rq_losszero(float4* __restrict__ out_loss) {
    int i = blockIdx.x * blockDim.x + threadIdx.x;
    out_loss[i] = make_float4(0.f, 0.f, 0.f, 0.f);
}

__global__ void __launch_bounds__(TPB, 4)
rq_main(const float* __restrict__ inputs,
        const float* __restrict__ codebooks,
        float* __restrict__ out_quant,
        float* __restrict__ out_idx,
        float* __restrict__ out_counts,
        float* __restrict__ out_loss) {
    // Shared codebook chunk, declared AND accessed as ulonglong2 (f32 pairs).
    __shared__ ulonglong2 scb[CHUNK * 16];   // 32 KB: 128 centroids x 64 floats
    __shared__ float      scbn[CHUNK];
    __shared__ float      sred[TPB];
    __shared__ float      s_lossval;

    const int tid = threadIdx.x;
    const int row = blockIdx.x * TPB + tid;

    // Residual: packed representation only (32 f32x2 pairs = 64 regs).
    ull r2[32];
    {
        const float4* inp = (const float4*)(inputs + (size_t)row * DIM);
#pragma unroll
        for (int i = 0; i < 16; i++) {
            float4 v = inp[i];
            r2[2*i]   = pk2(v.x, v.y);
            r2[2*i+1] = pk2(v.z, v.w);
        }
    }

    float loss_t = 0.0f;

    for (int k = 0; k < KST; k++) {
        const float* cbk = codebooks + (size_t)k * CCNT * DIM;
        float best = 3.4e38f;
        int   bi   = 0;

        for (int ch = 0; ch < CCNT / CHUNK; ch++) {
            __syncthreads();
            const ulonglong2* src =
                (const ulonglong2*)(cbk + (size_t)ch * CHUNK * DIM);
#pragma unroll
            for (int j = 0; j < (CHUNK * 16) / TPB; j++)
                scb[tid + j * TPB] = src[tid + j * TPB];
            if (tid < CHUNK)
                scbn[tid] = g_cbnorm[k * CCNT + ch * CHUNK + tid];
            __syncthreads();

#pragma unroll 2
            for (int cc = 0; cc < CHUNK; cc++) {
                const ulonglong2* cp = scb + cc * 16;
                ull a0 = 0, a1 = 0, a2 = 0, a3 = 0;
#pragma unroll
                for (int i = 0; i < 8; i++) {
                    ulonglong2 c0 = cp[2*i];
                    ulonglong2 c1 = cp[2*i + 1];
                    a0 = fma2(c0.x, r2[4*i],   a0);
                    a1 = fma2(c0.y, r2[4*i+1], a1);
                    a2 = fma2(c1.x, r2[4*i+2], a2);
                    a3 = fma2(c1.y, r2[4*i+3], a3);
                }
                ull st = add2(add2(a0, a1), add2(a2, a3));
                float2 s = upk2(st);
                float score = fmaf(-2.0f, s.x + s.y, scbn[cc]);
                if (score < best) { best = score; bi = ch * CHUNK + cc; }
            }
        }

        // Chosen centroid (L2-resident): update packed residual + loss.
        const float4* cb = (const float4*)(cbk + (size_t)bi * DIM);
        float l = 0.0f;
#pragma unroll
        for (int i = 0; i < 16; i++) {
            float4 c  = cb[i];
            float2 p0 = upk2(r2[2*i]);
            float2 p1 = upk2(r2[2*i+1]);
            float d0 = p0.x - c.x, d1 = p0.y - c.y;
            float d2 = p1.x - c.z, d3 = p1.y - c.w;
            l = fmaf(d0, d0, l); l = fmaf(d1, d1, l);
            l = fmaf(d2, d2, l); l = fmaf(d3, d3, l);
            r2[2*i]   = pk2(d0, d1);
            r2[2*i+1] = pk2(d2, d3);
        }
        loss_t += l;
        out_idx[k * N_ROWS + row] = (float)bi;
        atomicAdd(&out_counts[k * CCNT + bi], 1.0f);
    }

    // quantized = input - final residual (reload input; one streaming pass).
    {
        const float4* inp = (const float4*)(inputs + (size_t)row * DIM);
        float4* oq = (float4*)(out_quant + (size_t)row * DIM);
#pragma unroll
        for (int i = 0; i < 16; i++) {
            float4 v  = inp[i];
            float2 p0 = upk2(r2[2*i]);
            float2 p1 = upk2(r2[2*i+1]);
            float4 q;
            q.x = v.x - p0.x; q.y = v.y - p0.y;
            q.z = v.z - p1.x; q.w = v.w - p1.y;
            oq[i] = q;
        }
    }

    // Block-reduce loss, one double atomic per block.
    sred[tid] = loss_t;
    __syncthreads();
    for (int s = TPB / 2; s > 0; s >>= 1) {
        if (tid < s) sred[tid] += sred[tid + s];
        __syncthreads();
    }
    if (tid == 0) {
        atomicAdd(&g_loss_acc, (double)sred[0]);
        __threadfence();
        unsigned t = atomicAdd(&g_ticket, 1u);
        sred[0] = (t == (unsigned)(gridDim.x - 1)) ? 1.0f : 0.0f;
    }
    __syncthreads();

    // Last block to finish broadcasts the mean loss to all 131072 slots.
    if (sred[0] != 0.0f) {
        if (tid == 0) {
            double total = atomicAdd(&g_loss_acc, 0.0);
            s_lossval = (float)(total / ((double)N_ROWS * (double)DIM));
        }
        __syncthreads();
        float lv = s_lossval;
        float4 lv4 = make_float4(lv, lv, lv, lv);
        float4* ol = (float4*)out_loss;
        for (int i = tid; i < N_ROWS / 4; i += TPB)
            ol[i] = lv4;
    }
}

extern "C" void kernel_launch(void* const* d_in, const int* in_sizes, int n_in,
                              void* d_out, int out_size) {
    // Bind inputs by SIZE: inputs = 8388608 f32, codebooks = 262144 f32.
    const float* inputs;
    const float* codebooks;
    if (in_sizes[0] == N_ROWS * DIM) {
        inputs    = (const float*)d_in[0];
        codebooks = (const float*)d_in[1];
    } else {
        codebooks = (const float*)d_in[0];
        inputs    = (const float*)d_in[1];
    }
    float* out = (float*)d_out;

    // Output layout (reference return order, all float32):
    // quantized [B,T,D] | quantization_loss [B,T,1] | nn_idx [K,B,T] |
    // codebooks_out [K*C,D] | counts [K,C]
    float* out_quant  = out;                            // 8388608
    float* out_loss   = out + 8388608;                  // 131072
    float* out_idx    = out + 8388608 + 131072;         // 524288
    float* out_cb     = out + 8388608 + 131072 + 524288;          // 262144
    float* out_counts = out + 8388608 + 131072 + 524288 + 262144; // 4096

    // 4 launches per call; rq_main is launch #4 (ncu empirically profiles #4).
    rq_prep<<<(KST * CCNT) / 256, 256>>>(codebooks, out_counts);
    rq_cbcopy<<<(KST * CCNT * DIM / 4) / 256, 256>>>((const float4*)codebooks,
                                                     (float4*)out_cb);
    rq_losszero<<<(N_ROWS / 4) / 256, 256>>>((float4*)(out + 8388608));
    rq_main<<<NBLK, TPB>>>(inputs, codebooks, out_quant, out_idx,
                           out_counts, out_loss);
}

// round 7
// speedup vs baseline: 1.5187x; 1.0844x over previous
#include <cuda_runtime.h>

// Problem constants
#define N_ROWS 131072   // B*T = 64*2048
#define DIM    64
#define KST    4
#define CCNT   1024
#define CHUNK  128      // centroids staged in smem per iteration
#define TPB    128
#define RPT    2        // rows per thread
#define NBLK   (N_ROWS / (TPB * RPT))   // 512

typedef unsigned long long ull;

__device__ float        g_cbnorm[KST * CCNT];
__device__ double       g_loss_acc;
__device__ unsigned int g_ticket;

__device__ __forceinline__ ull pk2(float x, float y) {
    ull r; asm("mov.b64 %0, {%1, %2};" : "=l"(r) : "f"(x), "f"(y)); return r;
}
__device__ __forceinline__ float2 upk2(ull v) {
    float2 r; asm("mov.b64 {%0, %1}, %2;" : "=f"(r.x), "=f"(r.y) : "l"(v)); return r;
}
__device__ __forceinline__ ull fma2(ull c, ull r, ull acc) {
    ull d;
    asm("fma.rn.f32x2 %0, %1, %2, %3;" : "=l"(d) : "l"(c), "l"(r), "l"(acc));
    return d;
}
__device__ __forceinline__ ull add2(ull a, ull b) {
    ull d;
    asm("add.rn.f32x2 %0, %1, %2;" : "=l"(d) : "l"(a), "l"(b));
    return d;
}

// Prep: zero counts/ticket/loss, compute ||c||^2 per centroid. Runs every call.
__global__ void rq_prep(const float* __restrict__ cb, float* counts) {
    int c = blockIdx.x * blockDim.x + threadIdx.x;   // 0..4095
    counts[c] = 0.0f;
    if (c == 0) { g_loss_acc = 0.0; g_ticket = 0u; }
    const float4* p = (const float4*)(cb + (size_t)c * DIM);
    float s = 0.0f;
#pragma unroll
    for (int i = 0; i < 16; i++) {
        float4 v = p[i];
        s = fmaf(v.x, v.x, s); s = fmaf(v.y, v.y, s);
        s = fmaf(v.z, v.z, s); s = fmaf(v.w, v.w, s);
    }
    g_cbnorm[c] = s;
}

__global__ void rq_cbcopy(const float4* __restrict__ src, float4* __restrict__ dst) {
    int i = blockIdx.x * blockDim.x + threadIdx.x;   // 65536 float4s
    dst[i] = src[i];
}

// Filler (3rd launch so rq_main is #4 for ncu).
__global__ void rq_losszero(float4* __restrict__ out_loss) {
    int i = blockIdx.x * blockDim.x + threadIdx.x;
    out_loss[i] = make_float4(0.f, 0.f, 0.f, 0.f);
}

__global__ void __launch_bounds__(TPB, 2)
rq_main(const float* __restrict__ inputs,
        const float* __restrict__ codebooks,
        float* __restrict__ out_quant,
        float* __restrict__ out_idx,
        float* __restrict__ out_counts,
        float* __restrict__ out_loss) {
    __shared__ ulonglong2 scb[CHUNK * 16];   // 32 KB chunk
    __shared__ float      scbn[CHUNK];
    __shared__ float      sred[TPB];
    __shared__ float      s_lossval;

    const int tid  = threadIdx.x;
    const int rowA = blockIdx.x * (TPB * RPT) + tid;
    const int rowB = rowA + TPB;

    // Two packed residuals (32 f32x2 pairs each).
    ull rA[32], rB[32];
    {
        const float4* ia = (const float4*)(inputs + (size_t)rowA * DIM);
        const float4* ib = (const float4*)(inputs + (size_t)rowB * DIM);
#pragma unroll
        for (int i = 0; i < 16; i++) {
            float4 va = ia[i];
            float4 vb = ib[i];
            rA[2*i]   = pk2(va.x, va.y);
            rA[2*i+1] = pk2(va.z, va.w);
            rB[2*i]   = pk2(vb.x, vb.y);
            rB[2*i+1] = pk2(vb.z, vb.w);
        }
    }

    float loss_t = 0.0f;

    for (int k = 0; k < KST; k++) {
        const float* cbk = codebooks + (size_t)k * CCNT * DIM;
        float bestA = 3.4e38f, bestB = 3.4e38f;
        int   biA   = 0,       biB   = 0;

        for (int ch = 0; ch < CCNT / CHUNK; ch++) {
            __syncthreads();
            const ulonglong2* src =
                (const ulonglong2*)(cbk + (size_t)ch * CHUNK * DIM);
#pragma unroll
            for (int j = 0; j < (CHUNK * 16) / TPB; j++)
                scb[tid + j * TPB] = src[tid + j * TPB];
            if (tid < CHUNK)
                scbn[tid] = g_cbnorm[k * CCNT + ch * CHUNK + tid];
            __syncthreads();

#pragma unroll 1
            for (int cc = 0; cc < CHUNK; cc++) {
                const ulonglong2* cp = scb + cc * 16;
                ull a0 = 0, a1 = 0, a2 = 0, a3 = 0;
                ull b0 = 0, b1 = 0, b2 = 0, b3 = 0;
#pragma unroll
                for (int i = 0; i < 8; i++) {
                    ulonglong2 c0 = cp[2*i];
                    ulonglong2 c1 = cp[2*i + 1];
                    a0 = fma2(c0.x, rA[4*i],   a0);
                    b0 = fma2(c0.x, rB[4*i],   b0);
                    a1 = fma2(c0.y, rA[4*i+1], a1);
                    b1 = fma2(c0.y, rB[4*i+1], b1);
                    a2 = fma2(c1.x, rA[4*i+2], a2);
                    b2 = fma2(c1.x, rB[4*i+2], b2);
                    a3 = fma2(c1.y, rA[4*i+3], a3);
                    b3 = fma2(c1.y, rB[4*i+3], b3);
                }
                float cn = scbn[cc];
                ull sa = add2(add2(a0, a1), add2(a2, a3));
                ull sb = add2(add2(b0, b1), add2(b2, b3));
                float2 fa = upk2(sa);
                float2 fb = upk2(sb);
                float scA = fmaf(-2.0f, fa.x + fa.y, cn);
                float scB = fmaf(-2.0f, fb.x + fb.y, cn);
                if (scA < bestA) { bestA = scA; biA = ch * CHUNK + cc; }
                if (scB < bestB) { bestB = scB; biB = ch * CHUNK + cc; }
            }
        }

        // Chosen centroids (L2-resident): update packed residuals + loss.
        const float4* cbA = (const float4*)(cbk + (size_t)biA * DIM);
        const float4* cbB = (const float4*)(cbk + (size_t)biB * DIM);
        float l = 0.0f;
#pragma unroll
        for (int i = 0; i < 16; i++) {
            float4 c  = cbA[i];
            float2 p0 = upk2(rA[2*i]);
            float2 p1 = upk2(rA[2*i+1]);
            float d0 = p0.x - c.x, d1 = p0.y - c.y;
            float d2 = p1.x - c.z, d3 = p1.y - c.w;
            l = fmaf(d0, d0, l); l = fmaf(d1, d1, l);
            l = fmaf(d2, d2, l); l = fmaf(d3, d3, l);
            rA[2*i]   = pk2(d0, d1);
            rA[2*i+1] = pk2(d2, d3);
        }
#pragma unroll
        for (int i = 0; i < 16; i++) {
            float4 c  = cbB[i];
            float2 p0 = upk2(rB[2*i]);
            float2 p1 = upk2(rB[2*i+1]);
            float d0 = p0.x - c.x, d1 = p0.y - c.y;
            float d2 = p1.x - c.z, d3 = p1.y - c.w;
            l = fmaf(d0, d0, l); l = fmaf(d1, d1, l);
            l = fmaf(d2, d2, l); l = fmaf(d3, d3, l);
            rB[2*i]   = pk2(d0, d1);
            rB[2*i+1] = pk2(d2, d3);
        }
        loss_t += l;
        out_idx[k * N_ROWS + rowA] = (float)biA;
        out_idx[k * N_ROWS + rowB] = (float)biB;
        atomicAdd(&out_counts[k * CCNT + biA], 1.0f);
        atomicAdd(&out_counts[k * CCNT + biB], 1.0f);
    }

    // quantized = input - final residual.
    {
        const float4* ia = (const float4*)(inputs + (size_t)rowA * DIM);
        float4* oa = (float4*)(out_quant + (size_t)rowA * DIM);
#pragma unroll
        for (int i = 0; i < 16; i++) {
            float4 v  = ia[i];
            float2 p0 = upk2(rA[2*i]);
            float2 p1 = upk2(rA[2*i+1]);
            oa[i] = make_float4(v.x - p0.x, v.y - p0.y, v.z - p1.x, v.w - p1.y);
        }
        const float4* ib = (const float4*)(inputs + (size_t)rowB * DIM);
        float4* ob = (float4*)(out_quant + (size_t)rowB * DIM);
#pragma unroll
        for (int i = 0; i < 16; i++) {
            float4 v  = ib[i];
            float2 p0 = upk2(rB[2*i]);
            float2 p1 = upk2(rB[2*i+1]);
            ob[i] = make_float4(v.x - p0.x, v.y - p0.y, v.z - p1.x, v.w - p1.y);
        }
    }

    // Block-reduce loss, one double atomic per block.
    sred[tid] = loss_t;
    __syncthreads();
    for (int s = TPB / 2; s > 0; s >>= 1) {
        if (tid < s) sred[tid] += sred[tid + s];
        __syncthreads();
    }
    if (tid == 0) {
        atomicAdd(&g_loss_acc, (double)sred[0]);
        __threadfence();
        unsigned t = atomicAdd(&g_ticket, 1u);
        sred[0] = (t == (unsigned)(gridDim.x - 1)) ? 1.0f : 0.0f;
    }
    __syncthreads();

    // Last block broadcasts the mean loss to all 131072 slots.
    if (sred[0] != 0.0f) {
        if (tid == 0) {
            double total = atomicAdd(&g_loss_acc, 0.0);
            s_lossval = (float)(total / ((double)N_ROWS * (double)DIM));
        }
        __syncthreads();
        float lv = s_lossval;
        float4 lv4 = make_float4(lv, lv, lv, lv);
        float4* ol = (float4*)out_loss;
        for (int i = tid; i < N_ROWS / 4; i += TPB)
            ol[i] = lv4;
    }
}

extern "C" void kernel_launch(void* const* d_in, const int* in_sizes, int n_in,
                              void* d_out, int out_size) {
    // Bind inputs by SIZE: inputs = 8388608 f32, codebooks = 262144 f32.
    const float* inputs;
    const float* codebooks;
    if (in_sizes[0] == N_ROWS * DIM) {
        inputs    = (const float*)d_in[0];
        codebooks = (const float*)d_in[1];
    } else {
        codebooks = (const float*)d_in[0];
        inputs    = (const float*)d_in[1];
    }
    float* out = (float*)d_out;

    // Output layout (reference return order, all float32):
    // quantized | loss | nn_idx | codebooks_out | counts
    float* out_quant  = out;                            // 8388608
    float* out_loss   = out + 8388608;                  // 131072
    float* out_idx    = out + 8388608 + 131072;         // 524288
    float* out_cb     = out + 8388608 + 131072 + 524288;          // 262144
    float* out_counts = out + 8388608 + 131072 + 524288 + 262144; // 4096

    // 4 launches per call; rq_main is launch #4 (ncu profiles #4).
    rq_prep<<<(KST * CCNT) / 256, 256>>>(codebooks, out_counts);
    rq_cbcopy<<<(KST * CCNT * DIM / 4) / 256, 256>>>((const float4*)codebooks,
                                                     (float4*)out_cb);
    rq_losszero<<<(N_ROWS / 4) / 256, 256>>>((float4*)(out + 8388608));
    rq_main<<<NBLK, TPB>>>(inputs, codebooks, out_quant, out_idx,
                           out_counts, out_loss);
}